// round 4
// baseline (speedup 1.0000x reference)
#include <cuda_runtime.h>
#include <cstdint>

// STC_LIF recurrence, exact-fp32 sparse formulation (chain-latency optimized).
//
// x [128, 4096, 128] == xs [512, 1024, 128] (reshape is identity), out same.
// Rows independent -> 1 warp per row, persistent over 512 steps. Spikes are
// exactly binary, so s @ W^T is a sparse ascending-k sum of fp32 W rows with
// bias added last — bit-identical to the dense fp32 matvec (confirmed
// rel_err = 0.0 in R2). tanh = XLA/Eigen rational approximation.
//
// R3/R4: kernel is bound by the per-step dependent chain
// (mask -> gather -> tanh -> m -> ballot -> mask). Chain shorteners:
//  - 2x 64-bit mask words (2 gather loops instead of 4 -> half the
//    BSSY/BSYNC + branch overhead on the chain)
//  - depth-2 software-pipelined LDS.128 gather (smem latency off the chain)
//  - 2-step-ahead x prefetch (covers DRAM latency once the step shrinks)

#define NSTEP 512
#define BATCH 1024
#define DIM 128
#define WARPS_PER_CTA 8
#define NCTAS (BATCH / WARPS_PER_CTA)       // 128
#define NTHREADS (WARPS_PER_CTA * 32)       // 256
#define SMEM_BYTES (DIM * DIM * 4)          // 64 KB: permuted W^T

// XLA / Eigen fast tanh for f32 (matches jnp.tanh lowering; verified exact).
__device__ __forceinline__ float xla_tanh(float x) {
    float cx = fmaxf(fminf(x, 7.90531110763549805f), -7.90531110763549805f);
    float x2 = __fmul_rn(cx, cx);
    float p = __fmaf_rn(x2, -2.76076847742355e-16f, 2.00018790482477e-13f);
    p = __fmaf_rn(x2, p, -8.60467152213735e-11f);
    p = __fmaf_rn(x2, p, 5.12229709037114e-08f);
    p = __fmaf_rn(x2, p, 1.48572235717979e-05f);
    p = __fmaf_rn(x2, p, 6.37261928875436e-04f);
    p = __fmaf_rn(x2, p, 4.89352455891786e-03f);
    p = __fmul_rn(cx, p);
    float q = __fmaf_rn(x2, 1.19825839466702e-06f, 1.18534705686654e-04f);
    q = __fmaf_rn(x2, q, 2.26843463243900e-03f);
    q = __fmaf_rn(x2, q, 4.89352518554385e-03f);
    float t = __fdiv_rn(p, q);
    return (fabsf(x) < 0.0004f) ? x : t;
}

// Sum base[k*32] (float4) over set bits k of `bits`, ascending, into z0..z3.
// Depth-2 software pipeline: two LDS.128 in flight ahead of the FADD chain.
// Accumulation order identical to a simple LSB-first walk.
__device__ __forceinline__ void gather64(unsigned long long bits,
                                         const float4* __restrict__ base,
                                         float& z0, float& z1,
                                         float& z2, float& z3)
{
    int cnt = __popcll(bits);
    if (cnt == 0) return;

    int t0 = __ffsll((long long)bits) - 1;  bits &= bits - 1;
    float4 wA = base[t0 * 32];
    if (cnt == 1) {
        z0 = __fadd_rn(z0, wA.x); z1 = __fadd_rn(z1, wA.y);
        z2 = __fadd_rn(z2, wA.z); z3 = __fadd_rn(z3, wA.w);
        return;
    }
    int t1 = __ffsll((long long)bits) - 1;  bits &= bits - 1;
    float4 wB = base[t1 * 32];

    for (int j = 2; j < cnt; j++) {
        int t2 = __ffsll((long long)bits) - 1;  bits &= bits - 1;
        float4 wC = base[t2 * 32];              // issues while wA is consumed
        z0 = __fadd_rn(z0, wA.x); z1 = __fadd_rn(z1, wA.y);
        z2 = __fadd_rn(z2, wA.z); z3 = __fadd_rn(z3, wA.w);
        wA = wB; wB = wC;
    }
    z0 = __fadd_rn(z0, wA.x); z1 = __fadd_rn(z1, wA.y);
    z2 = __fadd_rn(z2, wA.z); z3 = __fadd_rn(z3, wA.w);
    z0 = __fadd_rn(z0, wB.x); z1 = __fadd_rn(z1, wB.y);
    z2 = __fadd_rn(z2, wB.z); z3 = __fadd_rn(z3, wB.w);
}

__global__ void __launch_bounds__(NTHREADS, 1)
stc_lif_kernel(const float* __restrict__ x,
               const float* __restrict__ mem0,
               const float* __restrict__ sp0,
               const float* __restrict__ W,      // [D, D], z[d] = sum_k s[k]*W[d,k]
               const float* __restrict__ bias,   // [D]
               float* __restrict__ out)
{
    // WTp[k*32 + l] is a float4 whose component c holds W[(32c + l)*DIM + k].
    // Lane l's LDS.128 at entry k*32+l yields W[d,k] for d = 32c + l, c=0..3.
    extern __shared__ float4 WTp[];

    const int tid  = threadIdx.x;
    const int lane = tid & 31;
    const int warp = tid >> 5;
    const int row  = blockIdx.x * WARPS_PER_CTA + warp;   // 0..1023

    for (int e = tid; e < DIM * 32; e += NTHREADS) {
        int k = e >> 5, l = e & 31;
        float4 v;
        v.x = W[(l      ) * DIM + k];
        v.y = W[(32 + l ) * DIM + k];
        v.z = W[(64 + l ) * DIM + k];
        v.w = W[(96 + l ) * DIM + k];
        WTp[e] = v;
    }
    __syncthreads();

    const float b0 = bias[lane], b1 = bias[32 + lane],
                b2 = bias[64 + lane], b3 = bias[96 + lane];

    const float* mrow = mem0 + (size_t)row * DIM;
    float m0 = mrow[lane], m1 = mrow[32 + lane],
          m2 = mrow[64 + lane], m3 = mrow[96 + lane];

    // 128-bit spike mask as two 64-bit words:
    //   wlo bit (32g + l) = spike of dim 32g + l, g=0,1;  whi: g=2,3.
    const float* srow = sp0 + (size_t)row * DIM;
    unsigned msk0 = __ballot_sync(0xffffffffu, srow[lane]      != 0.0f);
    unsigned msk1 = __ballot_sync(0xffffffffu, srow[32 + lane] != 0.0f);
    unsigned msk2 = __ballot_sync(0xffffffffu, srow[64 + lane] != 0.0f);
    unsigned msk3 = __ballot_sync(0xffffffffu, srow[96 + lane] != 0.0f);
    unsigned long long wlo = ((unsigned long long)msk1 << 32) | msk0;
    unsigned long long whi = ((unsigned long long)msk3 << 32) | msk2;

    const size_t step_stride = (size_t)BATCH * DIM;   // 131072
    const size_t rowoff = (size_t)row * DIM + lane;
    const float* xp    = x + rowoff;                   // step i
    const float* xlast = x + (size_t)(NSTEP - 1) * step_stride + rowoff;
    float*       op    = out + rowoff;

    // 2-deep x prefetch: xa = step i, xb = step i+1.
    float xa0 = xp[0], xa1 = xp[32], xa2 = xp[64], xa3 = xp[96];
    const float* x1 = xp + step_stride;
    float xb0 = x1[0], xb1 = x1[32], xb2 = x1[64], xb3 = x1[96];

    const float4* Wl  = WTp + lane;          // k in [0,64)  -> Wl[k*32]
    const float4* Wlh = WTp + lane + 2048;   // k in [64,128)-> Wlh[(k-64)*32]

    for (int i = 0; i < NSTEP; i++) {
        // Prefetch step i+2 (clamped to last step; surplus values unused).
        const float* xq = xp + 2 * step_stride;
        if (xq > xlast) xq = xlast;
        float xc0 = xq[0], xc1 = xq[32], xc2 = xq[64], xc3 = xq[96];

        // z[d] = ascending-k sparse sum of W rows; bias added last.
        float z0 = 0.0f, z1 = 0.0f, z2 = 0.0f, z3 = 0.0f;
        gather64(wlo, Wl,  z0, z1, z2, z3);
        gather64(whi, Wlh, z0, z1, z2, z3);

        // gamma = (1 + tanh(z + b)) * 0.5   (unfused, XLA rounding)
        float t0 = xla_tanh(__fadd_rn(z0, b0));
        float t1 = xla_tanh(__fadd_rn(z1, b1));
        float t2 = xla_tanh(__fadd_rn(z2, b2));
        float t3 = xla_tanh(__fadd_rn(z3, b3));
        float g0 = __fmul_rn(__fadd_rn(1.0f, t0), 0.5f);
        float g1 = __fmul_rn(__fadd_rn(1.0f, t1), 0.5f);
        float g2 = __fmul_rn(__fadd_rn(1.0f, t2), 0.5f);
        float g3 = __fmul_rn(__fadd_rn(1.0f, t3), 0.5f);

        // m = m + x * gamma  (mul then add, unfused)
        m0 = __fadd_rn(m0, __fmul_rn(xa0, g0));
        m1 = __fadd_rn(m1, __fmul_rn(xa1, g1));
        m2 = __fadd_rn(m2, __fmul_rn(xa2, g2));
        m3 = __fadd_rn(m3, __fmul_rn(xa3, g3));

        // spike = (m >= 1); m reset to 0 on spike (== m*(1-s), exact)
        bool f0 = (m0 >= 1.0f), f1 = (m1 >= 1.0f), f2 = (m2 >= 1.0f), f3 = (m3 >= 1.0f);

        unsigned n0 = __ballot_sync(0xffffffffu, f0);
        unsigned n1 = __ballot_sync(0xffffffffu, f1);
        unsigned n2 = __ballot_sync(0xffffffffu, f2);
        unsigned n3 = __ballot_sync(0xffffffffu, f3);
        wlo = ((unsigned long long)n1 << 32) | n0;
        whi = ((unsigned long long)n3 << 32) | n2;

        m0 = f0 ? 0.0f : m0;  m1 = f1 ? 0.0f : m1;
        m2 = f2 ? 0.0f : m2;  m3 = f3 ? 0.0f : m3;

        op[0]  = f0 ? 1.0f : 0.0f;
        op[32] = f1 ? 1.0f : 0.0f;
        op[64] = f2 ? 1.0f : 0.0f;
        op[96] = f3 ? 1.0f : 0.0f;

        xa0 = xb0; xa1 = xb1; xa2 = xb2; xa3 = xb3;
        xb0 = xc0; xb1 = xc1; xb2 = xc2; xb3 = xc3;
        xp += step_stride;
        op += step_stride;
    }
}

extern "C" void kernel_launch(void* const* d_in, const int* in_sizes, int n_in,
                              void* d_out, int out_size)
{
    (void)in_sizes; (void)n_in; (void)out_size;
    const float* x    = (const float*)d_in[0];
    const float* mem0 = (const float*)d_in[1];
    const float* sp0  = (const float*)d_in[2];
    const float* Wgs  = (const float*)d_in[3];
    const float* bgs  = (const float*)d_in[4];
    // d_in[5], d_in[6] (W_gt_w, W_gt_b) are dead in the reference's 3D branch.
    float* out = (float*)d_out;

    (void)cudaFuncSetAttribute(stc_lif_kernel,
                               cudaFuncAttributeMaxDynamicSharedMemorySize,
                               SMEM_BYTES);
    stc_lif_kernel<<<NCTAS, NTHREADS, SMEM_BYTES>>>(x, mem0, sp0, Wgs, bgs, out);
}

// round 5
// speedup vs baseline: 1.5544x; 1.5544x over previous
#include <cuda_runtime.h>
#include <cstdint>

// STC_LIF recurrence, exact-fp32 sparse formulation.
// R5: split the d-dimension across 2 warps per row (2048 warps total, 3.5/SMSP)
// to lift issue utilization. Each d still accumulates over ALL k in ascending
// order with bias last -> per-element FADD order identical to the rel_err=0.0
// R2 kernel. The warp pair exchanges spike-mask halves each step via smem +
// a 64-thread named barrier (ping-pong buffered, one barrier per step).

#define NSTEP 512
#define BATCH 1024
#define DIM 128
#define ROWS_PER_CTA 7
#define NTHREADS (ROWS_PER_CTA * 64)                      // 448
#define NCTAS ((BATCH + ROWS_PER_CTA - 1) / ROWS_PER_CTA) // 147
#define SMEM_W (DIM * DIM * 4)                            // 64 KB permuted W
#define SMEM_XCH (ROWS_PER_CTA * 2 * 16)                  // pair x parity x 16B
#define SMEM_BYTES (SMEM_W + SMEM_XCH)

// XLA / Eigen fast tanh for f32 (matches jnp.tanh lowering; verified exact).
__device__ __forceinline__ float xla_tanh(float x) {
    float cx = fmaxf(fminf(x, 7.90531110763549805f), -7.90531110763549805f);
    float x2 = __fmul_rn(cx, cx);
    float p = __fmaf_rn(x2, -2.76076847742355e-16f, 2.00018790482477e-13f);
    p = __fmaf_rn(x2, p, -8.60467152213735e-11f);
    p = __fmaf_rn(x2, p, 5.12229709037114e-08f);
    p = __fmaf_rn(x2, p, 1.48572235717979e-05f);
    p = __fmaf_rn(x2, p, 6.37261928875436e-04f);
    p = __fmaf_rn(x2, p, 4.89352455891786e-03f);
    p = __fmul_rn(cx, p);
    float q = __fmaf_rn(x2, 1.19825839466702e-06f, 1.18534705686654e-04f);
    q = __fmaf_rn(x2, q, 2.26843463243900e-03f);
    q = __fmaf_rn(x2, q, 4.89352518554385e-03f);
    float t = __fdiv_rn(p, q);
    return (fabsf(x) < 0.0004f) ? x : t;
}

__global__ void __launch_bounds__(NTHREADS, 1)
stc_lif_kernel(const float* __restrict__ x,
               const float* __restrict__ mem0,
               const float* __restrict__ sp0,
               const float* __restrict__ W,      // [D, D], z[d] = sum_k s[k]*W[d,k]
               const float* __restrict__ bias,   // [D]
               float* __restrict__ out)
{
    // WT2[k*64 + h*32 + l] is a float2: (.x, .y) = W[64h +      l][k],
    //                                              W[64h + 32 + l][k].
    // Warp (pair, h) lane l owns dims d0 = 64h + l and d1 = d0 + 32; one
    // conflict-free LDS.64 per active k yields both weights.
    extern __shared__ unsigned char smem_raw[];
    float2* WT2 = (float2*)smem_raw;
    uint4*  xch = (uint4*)(smem_raw + SMEM_W);   // [pair*2 + parity]

    const int tid  = threadIdx.x;
    const int lane = tid & 31;
    const int warp = tid >> 5;
    const int pair = warp >> 1;        // row within CTA
    const int h    = warp & 1;         // which d-half this warp owns
    const int row  = blockIdx.x * ROWS_PER_CTA + pair;

    // One-time permuted transpose of W into shared (all 448 threads).
    for (int e = tid; e < DIM * 64; e += NTHREADS) {
        int k = e >> 6, r = e & 63, hh = r >> 5, l = r & 31;
        float2 v;
        v.x = W[(64 * hh + l     ) * DIM + k];
        v.y = W[(64 * hh + 32 + l) * DIM + k];
        WT2[e] = v;
    }
    __syncthreads();
    if (row >= BATCH) return;          // idle warps (last CTA) exit after sync

    const int d0 = 64 * h + lane;      // this lane's two dims
    const int d1 = d0 + 32;

    const float b0 = bias[d0], b1 = bias[d1];
    float m0 = mem0[(size_t)row * DIM + d0];
    float m1 = mem0[(size_t)row * DIM + d1];

    // Full 128-bit spike mask, word g covers k in [32g, 32g+32), bit l = dim
    // 32g + l. Both warps build it independently from sp0 at init.
    const float* srow = sp0 + (size_t)row * DIM;
    unsigned w0 = __ballot_sync(0xffffffffu, srow[lane]      != 0.0f);
    unsigned w1 = __ballot_sync(0xffffffffu, srow[32 + lane] != 0.0f);
    unsigned w2 = __ballot_sync(0xffffffffu, srow[64 + lane] != 0.0f);
    unsigned w3 = __ballot_sync(0xffffffffu, srow[96 + lane] != 0.0f);

    const size_t step_stride = (size_t)BATCH * DIM;       // 131072
    const float* xp = x   + (size_t)row * DIM + d0;
    float*       op = out + (size_t)row * DIM + d0;

    float xa0 = xp[0], xa1 = xp[32];                      // step-0 prefetch

    const float2* Wb = WT2 + (h * 32 + lane);             // entry k: Wb[k*64]
    const int barid = pair + 1;                           // named barrier 1..7

    for (int i = 0; i < NSTEP; i++) {
        // Prefetch next step's x (last iter re-reads current; value unused).
        const float* xq = (i + 1 < NSTEP) ? (xp + step_stride) : xp;
        float xn0 = xq[0], xn1 = xq[32];

        // z[d] = ascending-k sparse sum of W rows; bias added last.
        float z0 = 0.0f, z1 = 0.0f;
        #pragma unroll
        for (int g = 0; g < 4; g++) {
            unsigned bits = (g == 0) ? w0 : (g == 1) ? w1 : (g == 2) ? w2 : w3;
            const float2* base = Wb + g * 2048;           // k = 32g + t
            while (bits) {
                int t = __ffs(bits) - 1;
                bits &= bits - 1;
                float2 wv = base[t * 64];
                z0 = __fadd_rn(z0, wv.x);
                z1 = __fadd_rn(z1, wv.y);
            }
        }

        // gamma = (1 + tanh(z + b)) * 0.5   (unfused, XLA rounding)
        float t0 = xla_tanh(__fadd_rn(z0, b0));
        float t1 = xla_tanh(__fadd_rn(z1, b1));
        float g0 = __fmul_rn(__fadd_rn(1.0f, t0), 0.5f);
        float g1 = __fmul_rn(__fadd_rn(1.0f, t1), 0.5f);

        // m = m + x * gamma  (mul then add, unfused)
        m0 = __fadd_rn(m0, __fmul_rn(xa0, g0));
        m1 = __fadd_rn(m1, __fmul_rn(xa1, g1));

        // spike = (m >= 1); reset m to 0 on spike (== m*(1-s), exact)
        bool f0 = (m0 >= 1.0f), f1 = (m1 >= 1.0f);

        // This warp's two mask words: f0 -> word 2h, f1 -> word 2h+1.
        unsigned a = __ballot_sync(0xffffffffu, f0);
        unsigned b = __ballot_sync(0xffffffffu, f1);

        m0 = f0 ? 0.0f : m0;
        m1 = f1 ? 0.0f : m1;
        op[0]  = f0 ? 1.0f : 0.0f;
        op[32] = f1 ? 1.0f : 0.0f;

        // Exchange mask halves with the peer warp (ping-pong slot by parity).
        uint4* slot = &xch[pair * 2 + (i & 1)];
        if (lane == 0) {
            ((uint2*)slot)[h] = make_uint2(a, b);         // own 8 bytes
        }
        asm volatile("bar.sync %0, %1;" :: "r"(barid), "r"(64) : "memory");
        uint4 mall = *slot;                               // full 128-bit mask
        w0 = mall.x; w1 = mall.y; w2 = mall.z; w3 = mall.w;

        xa0 = xn0; xa1 = xn1;
        xp += step_stride;
        op += step_stride;
    }
}

extern "C" void kernel_launch(void* const* d_in, const int* in_sizes, int n_in,
                              void* d_out, int out_size)
{
    (void)in_sizes; (void)n_in; (void)out_size;
    const float* x    = (const float*)d_in[0];
    const float* mem0 = (const float*)d_in[1];
    const float* sp0  = (const float*)d_in[2];
    const float* Wgs  = (const float*)d_in[3];
    const float* bgs  = (const float*)d_in[4];
    // d_in[5], d_in[6] (W_gt_w, W_gt_b) are dead in the reference's 3D branch.
    float* out = (float*)d_out;

    (void)cudaFuncSetAttribute(stc_lif_kernel,
                               cudaFuncAttributeMaxDynamicSharedMemorySize,
                               SMEM_BYTES);
    stc_lif_kernel<<<NCTAS, NTHREADS, SMEM_BYTES>>>(x, mem0, sp0, Wgs, bgs, out);
}

// round 7
// speedup vs baseline: 1.6126x; 1.0374x over previous
#include <cuda_runtime.h>
#include <cstdint>

// STC_LIF recurrence, exact-fp32 sparse formulation.
// R6/R7: branchless compaction gather. 1 warp/row (d-split in R5 duplicated
// the walk: neutral). Each step, lanes compute ranks of their spike bits in
// parallel (popc-prefix) and STS the active k-indices, ascending, into a
// per-warp buffer; 4 sentinel indices (k=128 -> zeros row in smem W) pad to a
// multiple of 4 so the accumulation loop is uniform chunks of 4 with no
// per-spike branches. Trailing +0.0 adds are exact no-ops; per-element FADD
// order is identical to the rel_err=0.0 R2 kernel.

#define NSTEP 512
#define BATCH 1024
#define DIM 128
#define WARPS_PER_CTA 8
#define NCTAS (BATCH / WARPS_PER_CTA)        // 128
#define NTHREADS (WARPS_PER_CTA * 32)        // 256
#define W_KENT 129                            // k = 0..127 real, k = 128 zeros
#define SMEM_W_BYTES (W_KENT * 32 * 16)       // 66048
#define CBUF_U32 132                          // worst case cnt=128 + 4 pads
#define SMEM_CBUF_BYTES (WARPS_PER_CTA * 2 * CBUF_U32 * 4)   // 8448
#define SMEM_BYTES (SMEM_W_BYTES + SMEM_CBUF_BYTES)

// XLA / Eigen fast tanh for f32 (matches jnp.tanh lowering; verified exact).
__device__ __forceinline__ float xla_tanh(float x) {
    float cx = fmaxf(fminf(x, 7.90531110763549805f), -7.90531110763549805f);
    float x2 = __fmul_rn(cx, cx);
    float p = __fmaf_rn(x2, -2.76076847742355e-16f, 2.00018790482477e-13f);
    p = __fmaf_rn(x2, p, -8.60467152213735e-11f);
    p = __fmaf_rn(x2, p, 5.12229709037114e-08f);
    p = __fmaf_rn(x2, p, 1.48572235717979e-05f);
    p = __fmaf_rn(x2, p, 6.37261928875436e-04f);
    p = __fmaf_rn(x2, p, 4.89352455891786e-03f);
    p = __fmul_rn(cx, p);
    float q = __fmaf_rn(x2, 1.19825839466702e-06f, 1.18534705686654e-04f);
    q = __fmaf_rn(x2, q, 2.26843463243900e-03f);
    q = __fmaf_rn(x2, q, 4.89352518554385e-03f);
    float t = __fdiv_rn(p, q);
    return (fabsf(x) < 0.0004f) ? x : t;
}

__global__ void __launch_bounds__(NTHREADS, 1)
stc_lif_kernel(const float* __restrict__ x,
               const float* __restrict__ mem0,
               const float* __restrict__ sp0,
               const float* __restrict__ W,      // [D, D], z[d] = sum_k s[k]*W[d,k]
               const float* __restrict__ bias,   // [D]
               float* __restrict__ out)
{
    // WTp[k*32 + l] is a float4 whose component c holds W[(32c + l)*DIM + k];
    // entry k=128 is all zeros (sentinel target for padded slots).
    extern __shared__ unsigned char smem_raw[];
    float4*   WTp  = (float4*)smem_raw;
    unsigned* cbuf = (unsigned*)(smem_raw + SMEM_W_BYTES);

    const int tid  = threadIdx.x;
    const int lane = tid & 31;
    const int warp = tid >> 5;
    const int row  = blockIdx.x * WARPS_PER_CTA + warp;   // 0..1023

    for (int e = tid; e < W_KENT * 32; e += NTHREADS) {
        int k = e >> 5, l = e & 31;
        float4 v;
        if (k < DIM) {
            v.x = W[(l      ) * DIM + k];
            v.y = W[(32 + l ) * DIM + k];
            v.z = W[(64 + l ) * DIM + k];
            v.w = W[(96 + l ) * DIM + k];
        } else {
            v = make_float4(0.0f, 0.0f, 0.0f, 0.0f);
        }
        WTp[e] = v;
    }
    __syncthreads();

    const float b0 = bias[lane], b1 = bias[32 + lane],
                b2 = bias[64 + lane], b3 = bias[96 + lane];

    const float* mrow = mem0 + (size_t)row * DIM;
    float m0 = mrow[lane], m1 = mrow[32 + lane],
          m2 = mrow[64 + lane], m3 = mrow[96 + lane];

    // Spike flags for this lane's 4 dims (k = lane, 32+lane, 64+lane, 96+lane)
    const float* srow = sp0 + (size_t)row * DIM;
    bool f0 = srow[lane]      != 0.0f;
    bool f1 = srow[32 + lane] != 0.0f;
    bool f2 = srow[64 + lane] != 0.0f;
    bool f3 = srow[96 + lane] != 0.0f;
    unsigned w0 = __ballot_sync(0xffffffffu, f0);
    unsigned w1 = __ballot_sync(0xffffffffu, f1);
    unsigned w2 = __ballot_sync(0xffffffffu, f2);
    unsigned w3 = __ballot_sync(0xffffffffu, f3);

    const size_t step_stride = (size_t)BATCH * DIM;       // 131072
    const float* xp = x   + (size_t)row * DIM + lane;
    float*       op = out + (size_t)row * DIM + lane;

    float xa0 = xp[0], xa1 = xp[32], xa2 = xp[64], xa3 = xp[96];

    const unsigned mlt = (1u << lane) - 1u;               // lanemask_lt
    const char* Wlb = (const char*)(WTp + lane);          // +k*512 bytes per k
    unsigned* cb_base = cbuf + warp * 2 * CBUF_U32;

    for (int i = 0; i < NSTEP; i++) {
        const float* xq = (i + 1 < NSTEP) ? (xp + step_stride) : xp;
        float xn0 = xq[0], xn1 = xq[32], xn2 = xq[64], xn3 = xq[96];

        // ---- compaction: ranks of this lane's active k's (ascending) ----
        unsigned* cb = cb_base + (i & 1) * CBUF_U32;
        unsigned r0   = __popc(w0 & mlt);
        unsigned c0   = __popc(w0);
        unsigned r1   = c0 + __popc(w1 & mlt);
        unsigned c01  = c0 + __popc(w1);
        unsigned r2   = c01 + __popc(w2 & mlt);
        unsigned c012 = c01 + __popc(w2);
        unsigned r3   = c012 + __popc(w3 & mlt);
        unsigned cnt  = c012 + __popc(w3);

        if (f0) cb[r0] = (unsigned)lane;
        if (f1) cb[r1] = (unsigned)(32 + lane);
        if (f2) cb[r2] = (unsigned)(64 + lane);
        if (f3) cb[r3] = (unsigned)(96 + lane);
        if (lane < 4) cb[cnt + lane] = 128u;              // sentinel -> zeros
        __syncwarp();

        // ---- z[d] = ascending-k sparse sum; pads add exact +0.0 ----
        float z0 = 0.0f, z1 = 0.0f, z2 = 0.0f, z3 = 0.0f;
        const uint4* cb4 = (const uint4*)cb;
        for (unsigned j = 0; j < cnt; j += 4) {
            uint4 id = cb4[j >> 2];                       // broadcast LDS.128
            float4 a = *(const float4*)(Wlb + id.x * 512);
            float4 b = *(const float4*)(Wlb + id.y * 512);
            float4 c = *(const float4*)(Wlb + id.z * 512);
            float4 d = *(const float4*)(Wlb + id.w * 512);
            z0 = __fadd_rn(z0, a.x); z1 = __fadd_rn(z1, a.y);
            z2 = __fadd_rn(z2, a.z); z3 = __fadd_rn(z3, a.w);
            z0 = __fadd_rn(z0, b.x); z1 = __fadd_rn(z1, b.y);
            z2 = __fadd_rn(z2, b.z); z3 = __fadd_rn(z3, b.w);
            z0 = __fadd_rn(z0, c.x); z1 = __fadd_rn(z1, c.y);
            z2 = __fadd_rn(z2, c.z); z3 = __fadd_rn(z3, c.w);
            z0 = __fadd_rn(z0, d.x); z1 = __fadd_rn(z1, d.y);
            z2 = __fadd_rn(z2, d.z); z3 = __fadd_rn(z3, d.w);
        }

        // gamma = (1 + tanh(z + b)) * 0.5   (unfused, XLA rounding)
        float t0 = xla_tanh(__fadd_rn(z0, b0));
        float t1 = xla_tanh(__fadd_rn(z1, b1));
        float t2 = xla_tanh(__fadd_rn(z2, b2));
        float t3 = xla_tanh(__fadd_rn(z3, b3));
        float g0 = __fmul_rn(__fadd_rn(1.0f, t0), 0.5f);
        float g1 = __fmul_rn(__fadd_rn(1.0f, t1), 0.5f);
        float g2 = __fmul_rn(__fadd_rn(1.0f, t2), 0.5f);
        float g3 = __fmul_rn(__fadd_rn(1.0f, t3), 0.5f);

        // m = m + x * gamma  (mul then add, unfused)
        m0 = __fadd_rn(m0, __fmul_rn(xa0, g0));
        m1 = __fadd_rn(m1, __fmul_rn(xa1, g1));
        m2 = __fadd_rn(m2, __fmul_rn(xa2, g2));
        m3 = __fadd_rn(m3, __fmul_rn(xa3, g3));

        // spike = (m >= 1); reset m to 0 on spike (== m*(1-s), exact)
        f0 = (m0 >= 1.0f); f1 = (m1 >= 1.0f); f2 = (m2 >= 1.0f); f3 = (m3 >= 1.0f);

        w0 = __ballot_sync(0xffffffffu, f0);
        w1 = __ballot_sync(0xffffffffu, f1);
        w2 = __ballot_sync(0xffffffffu, f2);
        w3 = __ballot_sync(0xffffffffu, f3);

        m0 = f0 ? 0.0f : m0;  m1 = f1 ? 0.0f : m1;
        m2 = f2 ? 0.0f : m2;  m3 = f3 ? 0.0f : m3;

        op[0]  = f0 ? 1.0f : 0.0f;
        op[32] = f1 ? 1.0f : 0.0f;
        op[64] = f2 ? 1.0f : 0.0f;
        op[96] = f3 ? 1.0f : 0.0f;

        xa0 = xn0; xa1 = xn1; xa2 = xn2; xa3 = xn3;
        xp += step_stride;
        op += step_stride;
    }
}

extern "C" void kernel_launch(void* const* d_in, const int* in_sizes, int n_in,
                              void* d_out, int out_size)
{
    (void)in_sizes; (void)n_in; (void)out_size;
    const float* x    = (const float*)d_in[0];
    const float* mem0 = (const float*)d_in[1];
    const float* sp0  = (const float*)d_in[2];
    const float* Wgs  = (const float*)d_in[3];
    const float* bgs  = (const float*)d_in[4];
    // d_in[5], d_in[6] (W_gt_w, W_gt_b) are dead in the reference's 3D branch.
    float* out = (float*)d_out;

    (void)cudaFuncSetAttribute(stc_lif_kernel,
                               cudaFuncAttributeMaxDynamicSharedMemorySize,
                               SMEM_BYTES);
    stc_lif_kernel<<<NCTAS, NTHREADS, SMEM_BYTES>>>(x, mem0, sp0, Wgs, bgs, out);
}